// round 13
// baseline (speedup 1.0000x reference)
#include <cuda_runtime.h>
#include <cuda_fp16.h>
#include <cstdint>

#define N_Q   8192
#define DIM   384
#define N_DOC 1024
#define KST   384           // fp16, both operands
#define K_ITERS 6           // 6 chunks of 64

// ---------------- scratch (static device globals; no allocation) -------------
__device__ float   g_C[(size_t)N_DOC * DIM];
__device__ float   g_den[N_DOC];
__device__ __half  g_A2[(size_t)N_Q  * KST];    // 6.3 MB
__device__ __half  g_B2[(size_t)N_DOC * KST];   // 0.8 MB
__device__ float   g_G[(size_t)N_Q * N_DOC];    // 33.5 MB (L2-resident)
__device__ int     g_cnt[64];                   // per-tm completion counters

// ---------------- helpers -----------------------------------------------------
__device__ __forceinline__ uint32_t smem_u32(const void* p) {
    uint32_t a;
    asm("{ .reg .u64 t; cvta.to.shared.u64 t, %1; cvt.u32.u64 %0, t; }" : "=r"(a) : "l"(p));
    return a;
}
__device__ __forceinline__ void cp16(uint32_t dst, const void* src) {
    asm volatile("cp.async.cg.shared.global [%0], [%1], 16;" :: "r"(dst), "l"(src));
}
__device__ __forceinline__ void cp_commit() { asm volatile("cp.async.commit_group;"); }
__device__ __forceinline__ void ldsm4(uint32_t& r0, uint32_t& r1, uint32_t& r2, uint32_t& r3,
                                      uint32_t addr) {
    asm volatile("ldmatrix.sync.aligned.m8n8.x4.shared.b16 {%0,%1,%2,%3}, [%4];"
                 : "=r"(r0), "=r"(r1), "=r"(r2), "=r"(r3) : "r"(addr));
}
__device__ __forceinline__ void mma16816(float* c, const uint32_t* a, const uint32_t* b) {
    asm volatile(
        "mma.sync.aligned.m16n8k16.row.col.f32.f16.f16.f32 "
        "{%0,%1,%2,%3}, {%4,%5,%6,%7}, {%8,%9}, {%0,%1,%2,%3};"
        : "+f"(c[0]), "+f"(c[1]), "+f"(c[2]), "+f"(c[3])
        : "r"(a[0]), "r"(a[1]), "r"(a[2]), "r"(a[3]), "r"(b[0]), "r"(b[1]));
}

// ---------------- kernel 0: zero accumulators + counters ----------------------
__global__ void k_zero() {
    int idx = blockIdx.x * 256 + threadIdx.x;
    if (idx < N_DOC * DIM) g_C[idx] = 0.0f;
    if (idx < N_DOC)       g_den[idx] = 0.0f;
    if (idx < 64)          g_cnt[idx] = 0;
}

// ---------------- kernel 1: normalize (warp/row) + fp16 A2 + segment acc -----
__global__ __launch_bounds__(256) void k_norm_acc(
    const float* __restrict__ emb, const float* __restrict__ label,
    const int* __restrict__ did)
{
    int i    = blockIdx.x * 8 + (threadIdx.x >> 5);   // row
    int lane = threadIdx.x & 31;

    const float4* row = (const float4*)(emb + (size_t)i * DIM);  // 96 float4
    float4 f0 = row[lane], f1 = row[lane + 32], f2 = row[lane + 64];
    float ss = f0.x*f0.x + f0.y*f0.y + f0.z*f0.z + f0.w*f0.w
             + f1.x*f1.x + f1.y*f1.y + f1.z*f1.z + f1.w*f1.w
             + f2.x*f2.x + f2.y*f2.y + f2.z*f2.z + f2.w*f2.w;
    #pragma unroll
    for (int o = 16; o > 0; o >>= 1) ss += __shfl_xor_sync(0xFFFFFFFFu, ss, o);
    float inv = rsqrtf(ss);

    __half2* arow = (__half2*)(g_A2 + (size_t)i * KST);
    arow[2*lane]            = __floats2half2_rn(f0.x*inv, f0.y*inv);
    arow[2*lane + 1]        = __floats2half2_rn(f0.z*inv, f0.w*inv);
    arow[64 + 2*lane]       = __floats2half2_rn(f1.x*inv, f1.y*inv);
    arow[64 + 2*lane + 1]   = __floats2half2_rn(f1.z*inv, f1.w*inv);
    arow[128 + 2*lane]      = __floats2half2_rn(f2.x*inv, f2.y*inv);
    arow[128 + 2*lane + 1]  = __floats2half2_rn(f2.z*inv, f2.w*inv);

    float w = label[i];
    int   j = did[i];
    float wi = w * inv;
    float* crow = g_C + (size_t)j * DIM;
    int c = 4 * lane;
    atomicAdd(&crow[c + 0],   wi * f0.x);
    atomicAdd(&crow[c + 1],   wi * f0.y);
    atomicAdd(&crow[c + 2],   wi * f0.z);
    atomicAdd(&crow[c + 3],   wi * f0.w);
    atomicAdd(&crow[c + 128], wi * f1.x);
    atomicAdd(&crow[c + 129], wi * f1.y);
    atomicAdd(&crow[c + 130], wi * f1.z);
    atomicAdd(&crow[c + 131], wi * f1.w);
    atomicAdd(&crow[c + 256], wi * f2.x);
    atomicAdd(&crow[c + 257], wi * f2.y);
    atomicAdd(&crow[c + 258], wi * f2.z);
    atomicAdd(&crow[c + 259], wi * f2.w);
    if (lane == 0) atomicAdd(&g_den[j], w);
}

// ---------------- kernel 2: B2 = fp16(C/den) ----------------------------------
__global__ __launch_bounds__(128) void k_scale() {
    int j = blockIdx.x;
    float inv = 1.0f / g_den[j];
    const float* crow = g_C + (size_t)j * DIM;
    __half* brow = g_B2 + (size_t)j * KST;
    for (int d = threadIdx.x; d < DIM; d += 128)
        brow[d] = __float2half(crow[d] * inv);
}

// ---------------- kernel 3: fused HMMA GEMM + last-arriver expand -------------
// GEMM: 128x128 CTA tile, 4 warps (2x2), warp tile 64x64, BK=64,
//       3-stage cp.async pipeline, rows 144B pitch (conflict-free ldmatrix).
// Expand: the 8th (last) CTA of each tm row-block gathers/writes theta rows.
#define BK        64
#define ROWB      144
#define STAGE_SB  (128 * ROWB)              // 18432 B per matrix per stage
#define STAGES    3
#define SM_TOTAL  (2 * STAGES * STAGE_SB)   // 110592 B (>= 48KB expand reuse)

__device__ __forceinline__ void issue_stage(
    int s, int buf, int tid, uint32_t sAu, uint32_t sBu,
    const __half* Abase, const __half* Bbase)
{
    int k0 = s * BK;
    uint32_t ad = sAu + buf * STAGE_SB;
    uint32_t bd = sBu + buf * STAGE_SB;
    #pragma unroll
    for (int j = 0; j < 8; ++j) {
        int idx = tid + j * 128;
        int r = idx >> 3, c = idx & 7;
        cp16(ad + r * ROWB + c * 16, Abase + (size_t)r * KST + k0 + c * 8);
        cp16(bd + r * ROWB + c * 16, Bbase + (size_t)r * KST + k0 + c * 8);
    }
    cp_commit();
}

__global__ __launch_bounds__(128, 2) void k_gemm(const int* __restrict__ did,
                                                 float* __restrict__ out)
{
    extern __shared__ __align__(128) char smem[];
    uint32_t sAu = smem_u32(smem);
    uint32_t sBu = sAu + STAGES * STAGE_SB;

    int tid  = threadIdx.x;
    int lane = tid & 31;
    int wid  = tid >> 5;
    int wm   = wid >> 1;
    int wn   = wid & 1;
    int tm = blockIdx.x;             // 0..63
    int tn = blockIdx.y;             // 0..7

    const __half* Abase = g_A2 + (size_t)(tm * 128) * KST;
    const __half* Bbase = g_B2 + (size_t)(tn * 128) * KST;

    float acc[4][8][4];
    #pragma unroll
    for (int i = 0; i < 4; i++)
        #pragma unroll
        for (int j = 0; j < 8; j++)
            #pragma unroll
            for (int v = 0; v < 4; v++) acc[i][j][v] = 0.0f;

    issue_stage(0, 0, tid, sAu, sBu, Abase, Bbase);
    issue_stage(1, 1, tid, sAu, sBu, Abase, Bbase);

    int a_row = wm * 64 + (lane & 15);
    int a_off = (lane >> 4) * 16;
    int b_row = wn * 64 + ((lane >> 4) * 8 + (lane & 7));
    int b_off = ((lane >> 3) & 1) * 16;

    #pragma unroll 1
    for (int it = 0; it < K_ITERS; ++it) {
        int buf = it % STAGES;

        if (it + 2 < K_ITERS)
            asm volatile("cp.async.wait_group 1;");
        else
            asm volatile("cp.async.wait_group 0;");
        __syncthreads();

        if (it + 2 < K_ITERS)
            issue_stage(it + 2, (it + 2) % STAGES, tid, sAu, sBu, Abase, Bbase);

        uint32_t sab = sAu + buf * STAGE_SB;
        uint32_t sbb = sBu + buf * STAGE_SB;

        #pragma unroll
        for (int kk = 0; kk < 4; ++kk) {
            uint32_t a[4][4];
            #pragma unroll
            for (int mi = 0; mi < 4; ++mi)
                ldsm4(a[mi][0], a[mi][1], a[mi][2], a[mi][3],
                      sab + (a_row + mi * 16) * ROWB + kk * 32 + a_off);
            uint32_t b[8][2];
            #pragma unroll
            for (int nt2 = 0; nt2 < 4; ++nt2) {
                uint32_t r0, r1, r2, r3;
                ldsm4(r0, r1, r2, r3,
                      sbb + (b_row + nt2 * 16) * ROWB + kk * 32 + b_off);
                b[nt2 * 2][0] = r0;     b[nt2 * 2][1] = r1;
                b[nt2 * 2 + 1][0] = r2; b[nt2 * 2 + 1][1] = r3;
            }
            #pragma unroll
            for (int mi = 0; mi < 4; ++mi)
                #pragma unroll
                for (int nj = 0; nj < 8; ++nj)
                    mma16816(acc[mi][nj], a[mi], b[nj]);
        }
    }

    // ---- epilogue: write 64x64 warp tile to g_G
    int rbase = tm * 128 + wm * 64 + (lane >> 2);
    int cbase = tn * 128 + wn * 64 + (lane & 3) * 2;
    #pragma unroll
    for (int mi = 0; mi < 4; ++mi) {
        #pragma unroll
        for (int nj = 0; nj < 8; ++nj) {
            int r = rbase + mi * 16;
            int c = cbase + nj * 8;
            *(float2*)(g_G + (size_t)r * N_DOC + c) =
                make_float2(acc[mi][nj][0], acc[mi][nj][1]);
            *(float2*)(g_G + (size_t)(r + 8) * N_DOC + c) =
                make_float2(acc[mi][nj][2], acc[mi][nj][3]);
        }
    }

    // ---- last-arriver election (release: fence before counted arrive) -------
    __threadfence();
    __syncthreads();                  // all threads' stores + fences done
    __shared__ int s_last;
    if (tid == 0) s_last = (atomicAdd(&g_cnt[tm], 1) == 7) ? 1 : 0;
    __syncthreads();
    if (!s_last) return;

    // ---- expansion for rows [tm*128, tm*128+128): theta[i,q] = G[i,did[q]] --
    // (no spin anywhere: the last arriver proceeds immediately; acquire via
    //  same-address RMW + the fence below; G read with __ldcg, never in our L1)
    __threadfence();
    int*    sdid = (int*)smem;                    // 32 KB  (pipeline smem dead)
    float4* sG4  = (float4*)(smem + 32768);       // 16 KB
    for (int q4 = tid; q4 < N_Q / 4; q4 += 128)
        ((int4*)sdid)[q4] = ((const int4*)did)[q4];

    #pragma unroll 1
    for (int g = 0; g < 32; ++g) {
        int i0 = tm * 128 + g * 4;
        __syncthreads();   // guards sdid (g==0) and sG4 reuse (g>0)
        for (int j = tid; j < N_DOC; j += 128) {
            sG4[j] = make_float4(__ldcg(&g_G[(size_t)(i0 + 0) * N_DOC + j]),
                                 __ldcg(&g_G[(size_t)(i0 + 1) * N_DOC + j]),
                                 __ldcg(&g_G[(size_t)(i0 + 2) * N_DOC + j]),
                                 __ldcg(&g_G[(size_t)(i0 + 3) * N_DOC + j]));
        }
        __syncthreads();

        const int4* sdid4 = (const int4*)sdid;
        float* o0 = out + (size_t)(i0 + 0) * N_Q;
        float* o1 = out + (size_t)(i0 + 1) * N_Q;
        float* o2 = out + (size_t)(i0 + 2) * N_Q;
        float* o3 = out + (size_t)(i0 + 3) * N_Q;
        #pragma unroll 2
        for (int q4 = tid; q4 < N_Q / 4; q4 += 128) {
            int4 d4 = sdid4[q4];
            float4 f0 = sG4[d4.x];
            float4 f1 = sG4[d4.y];
            float4 f2 = sG4[d4.z];
            float4 f3 = sG4[d4.w];
            ((float4*)o0)[q4] = make_float4(f0.x, f1.x, f2.x, f3.x);
            ((float4*)o1)[q4] = make_float4(f0.y, f1.y, f2.y, f3.y);
            ((float4*)o2)[q4] = make_float4(f0.z, f1.z, f2.z, f3.z);
            ((float4*)o3)[q4] = make_float4(f0.w, f1.w, f2.w, f3.w);
        }
    }
}

// ---------------- launch ------------------------------------------------------
extern "C" void kernel_launch(void* const* d_in, const int* in_sizes, int n_in,
                              void* d_out, int out_size)
{
    const float* emb   = (const float*)d_in[0];
    const float* label = (const float*)d_in[1];
    const int*   did   = (const int*)d_in[2];
    float*       out   = (float*)d_out;

    cudaFuncSetAttribute(k_gemm, cudaFuncAttributeMaxDynamicSharedMemorySize, SM_TOTAL);

    k_zero<<<(N_DOC * DIM + 255) / 256, 256>>>();
    k_norm_acc<<<N_Q / 8, 256>>>(emb, label, did);
    k_scale<<<N_DOC, 128>>>();
    k_gemm<<<dim3(64, 8), 128, SM_TOTAL>>>(did, out);
}